// round 13
// baseline (speedup 1.0000x reference)
#include <cuda_runtime.h>
#include <cuda_fp16.h>
#include <cstdint>

// Problem constants
#define CTXD   512
#define HIDD   2048
#define NCELLS 4096      // 64*64
#define NBATCH 8
#define KNN    8
#define MTOT   (NBATCH * NCELLS)   // 32768

// Scratch (allowed: __device__ globals)
__device__ __half g_aggh[(size_t)MTOT * CTXD];  // 32 MB fp16 agg
__device__ __half g_Wh[(size_t)HIDD * CTXD];    // 2 MB  fp16 W^T
// sync block: [0]=tile ctr, [1]=w items done, [2+mb]=agg items done per m-block
__device__ int    g_sync[2 + 256];

// ---------------------------------------------------------------------------
// GEMM tiling (R12/R9 proven core)
// ---------------------------------------------------------------------------
#define BM 128
#define BN 128
#define BK 64
#define NT (CTXD / BK)                        // 8 k-chunks per tile
#define NTILES ((MTOT / BM) * (HIDD / BN))    // 4096
#define SSTRIDE 72
#define TILE_H (128 * SSTRIDE)
#define STAGE_H (2 * TILE_H)
#define GEMM_SMEM (3 * STAGE_H * 2)           // 110592 bytes

#define GRID_CTAS 304
#define PREP_CTAS 152
#define N_AGG_ITEMS 4096                      // 8 cells per item
#define N_W_ITEMS   1024                      // 32x32 W tiles
#define ITEMS_PER_MB 16                       // 128 cells / 8

__device__ __forceinline__ void cpasync16(uint32_t saddr, const void* g) {
    asm volatile("cp.async.cg.shared.global [%0], [%1], 16;\n" :: "r"(saddr), "l"(g));
}
__device__ __forceinline__ void ldsm_x4(uint32_t& r0, uint32_t& r1,
                                        uint32_t& r2, uint32_t& r3, uint32_t a) {
    asm volatile("ldmatrix.sync.aligned.m8n8.x4.shared.b16 {%0,%1,%2,%3},[%4];"
                 : "=r"(r0), "=r"(r1), "=r"(r2), "=r"(r3) : "r"(a));
}

// ---------------- prep: W transpose item (32x32) ----------------
__device__ void do_wtrans_item(int wb, const float* __restrict__ W, char* smbuf) {
    float (*tile)[33] = reinterpret_cast<float (*)[33]>(smbuf);
    const int t  = threadIdx.x;
    const int bx = wb & 63;               // HIDD/32
    const int by = wb >> 6;               // CTXD/32
    const int tx = t & 31;
    const int ty = t >> 5;                // 0..7
#pragma unroll
    for (int i = 0; i < 4; i++)
        tile[ty + i * 8][tx] =
            W[(size_t)(by * 32 + ty + i * 8) * HIDD + bx * 32 + tx];
    __syncthreads();
#pragma unroll
    for (int i = 0; i < 4; i++)
        g_Wh[(size_t)(bx * 32 + ty + i * 8) * CTXD + by * 32 + tx] =
            __float2half(tile[tx][ty + i * 8]);
    __threadfence();
    __syncthreads();
    if (t == 0) atomicAdd(&g_sync[1], 1);
    __syncthreads();     // protect smem tile reuse by next item
}

// ---------------- prep: agg item (8 cells, one batch) ----------------
__device__ void do_agg_item(int item, const float* __restrict__ x,
                            const int* __restrict__ nn_idx,
                            const float* __restrict__ sim) {
    const int t    = threadIdx.x;
    const int b    = item >> 9;
    const int n0   = (item & 511) * 8;
    const int lane = t & 127;             // float4 lane
    const int sub  = t >> 7;              // 0/1: cell group

    const float4* xb = reinterpret_cast<const float4*>(x) +
                       (size_t)b * NCELLS * (CTXD / 4);
    uint2* dst = reinterpret_cast<uint2*>(g_aggh);

#pragma unroll
    for (int c = 0; c < 4; c++) {
        const int n = n0 + sub * 4 + c;
        float4 acc = make_float4(0.f, 0.f, 0.f, 0.f);
#pragma unroll
        for (int k = 0; k < KNN; k++) {
            const int   ix = __ldg(&nn_idx[n * KNN + k]);
            const float s  = __ldg(&sim[n * KNN + k]);
            const float4 v = xb[(size_t)ix * (CTXD / 4) + lane];
            acc.x = fmaf(s, v.x, acc.x);
            acc.y = fmaf(s, v.y, acc.y);
            acc.z = fmaf(s, v.z, acc.z);
            acc.w = fmaf(s, v.w, acc.w);
        }
        __half2 h0 = __float22half2_rn(make_float2(acc.x, acc.y));
        __half2 h1 = __float22half2_rn(make_float2(acc.z, acc.w));
        uint2 p;
        p.x = *reinterpret_cast<uint32_t*>(&h0);
        p.y = *reinterpret_cast<uint32_t*>(&h1);
        dst[((size_t)b * NCELLS + n) * (CTXD / 4) + lane] = p;
    }
    __threadfence();
    __syncthreads();
    if (t == 0) atomicAdd(&g_sync[2 + b * 32 + (n0 >> 7)], 1);
}

__device__ __forceinline__ void wait_mb(int mb) {
    while (atomicAdd(&g_sync[2 + mb], 0) < ITEMS_PER_MB) __nanosleep(128);
}
__device__ __forceinline__ void wait_w() {
    while (atomicAdd(&g_sync[1], 0) < N_W_ITEMS) __nanosleep(128);
}

// ---------------------------------------------------------------------------
// Fused kernel: prep (CTAs < PREP_CTAS) then persistent GEMM (all CTAs)
// ---------------------------------------------------------------------------
__global__ __launch_bounds__(256, 2) void fused_kernel(
    const float* __restrict__ x,
    const float* __restrict__ W,
    const int*   __restrict__ nn_idx,
    const float* __restrict__ sim,
    float*       __restrict__ C)
{
    extern __shared__ __half sm[];
    __shared__ int sm_next;

    const int tid = threadIdx.x;
    const int bid = blockIdx.x;

    // ---------------- prep phase (wave-1 resident CTAs only) ----------------
    if (bid < PREP_CTAS) {
        for (int i = bid; i < N_W_ITEMS; i += PREP_CTAS)
            do_wtrans_item(i, W, reinterpret_cast<char*>(sm));
        for (int i = bid; i < N_AGG_ITEMS; i += PREP_CTAS)
            do_agg_item(i, x, nn_idx, sim);
    }

    // ---------------- persistent GEMM ----------------
    const __half* A = g_aggh;
    const __half* B = g_Wh;

    const int lane = tid & 31;
    const int warp = tid >> 5;
    const int wm   = warp & 3;
    const int wn   = warp >> 2;
    const int g    = lane >> 2;
    const int t4   = lane & 3;

    auto load_chunk = [&](int buf, int tile, int kt) {
        const int m0 = (tile >> 4) * BM;
        const int n0 = (tile & 15) * BN;
        __half* Asb = sm + buf * STAGE_H;
        __half* Bsb = Asb + TILE_H;
        const __half* Ag = A + (size_t)m0 * CTXD + kt * BK;
        const __half* Bg = B + (size_t)n0 * CTXD + kt * BK;
#pragma unroll
        for (int i = 0; i < 4; i++) {
            int idx = i * 256 + tid;
            int row = idx >> 3;
            int c8  = (idx & 7) * 8;
            cpasync16((uint32_t)__cvta_generic_to_shared(Asb + row * SSTRIDE + c8),
                      Ag + (size_t)row * CTXD + c8);
        }
#pragma unroll
        for (int i = 0; i < 4; i++) {
            int idx = i * 256 + tid;
            int row = idx >> 3;
            int c8  = (idx & 7) * 8;
            cpasync16((uint32_t)__cvta_generic_to_shared(Bsb + row * SSTRIDE + c8),
                      Bg + (size_t)row * CTXD + c8);
        }
        asm volatile("cp.async.commit_group;\n");
    };

    // first tile: acquire + wait on producers
    if (tid == 0) {
        int tl = atomicAdd(&g_sync[0], 1);
        if (tl < NTILES) {
            wait_w();
            wait_mb(tl >> 4);
            __threadfence();
        }
        sm_next = tl;
    }
    __syncthreads();
    int tile = sm_next;
    if (tile >= NTILES) return;

    load_chunk(0, tile, 0);
    load_chunk(1, tile, 1);
    int st = 0;
    int ahead = 1;

    const int a_r  = lane & 15;
    const int a_k  = (lane >> 4) * 8;
    const int b_r  = lane & 7;
    const int b_no = ((lane >> 3) >> 1) * 8;
    const int b_ko = ((lane >> 3) & 1) * 8;

    while (true) {
        float acc[2][8][4];
#pragma unroll
        for (int i = 0; i < 2; i++)
#pragma unroll
            for (int j = 0; j < 8; j++)
#pragma unroll
                for (int r = 0; r < 4; r++) acc[i][j][r] = 0.f;

        int next_tile = NTILES;

        for (int kt = 0; kt < NT; ++kt) {
            if (ahead > 0) asm volatile("cp.async.wait_group 1;\n");
            else           asm volatile("cp.async.wait_group 0;\n");
            __syncthreads();

            if (kt == NT - 3) {
                if (tid == 0) {
                    int nt = atomicAdd(&g_sync[0], 1);
                    if (nt < NTILES) {
                        wait_mb(nt >> 4);
                        __threadfence();
                    }
                    sm_next = nt;
                }
            }
            if (kt == NT - 2) next_tile = sm_next;

            if (kt + 2 < NT) {
                load_chunk((st + 2) % 3, tile, kt + 2);
                ahead = 2;
            } else if (next_tile < NTILES) {
                load_chunk((st + 2) % 3, next_tile, kt + 2 - NT);
                ahead = 2;
            }

            const __half* Asb = sm + st * STAGE_H;
            const __half* Bsb = Asb + TILE_H;

#pragma unroll
            for (int ks = 0; ks < 4; ++ks) {
                const int k0 = ks * 16;

                uint32_t af[2][4];
#pragma unroll
                for (int mi = 0; mi < 2; ++mi) {
                    uint32_t a = (uint32_t)__cvta_generic_to_shared(
                        Asb + (wm * 32 + mi * 16 + a_r) * SSTRIDE + k0 + a_k);
                    ldsm_x4(af[mi][0], af[mi][1], af[mi][2], af[mi][3], a);
                }
                uint32_t bf[8][2];
#pragma unroll
                for (int nj = 0; nj < 4; ++nj) {
                    uint32_t a = (uint32_t)__cvta_generic_to_shared(
                        Bsb + (wn * 64 + nj * 16 + b_no + b_r) * SSTRIDE + k0 + b_ko);
                    ldsm_x4(bf[2 * nj][0], bf[2 * nj][1],
                            bf[2 * nj + 1][0], bf[2 * nj + 1][1], a);
                }
#pragma unroll
                for (int mi = 0; mi < 2; ++mi)
#pragma unroll
                    for (int ni = 0; ni < 8; ++ni) {
                        asm volatile(
                            "mma.sync.aligned.m16n8k16.row.col.f32.f16.f16.f32 "
                            "{%0,%1,%2,%3},{%4,%5,%6,%7},{%8,%9},{%0,%1,%2,%3};\n"
                            : "+f"(acc[mi][ni][0]), "+f"(acc[mi][ni][1]),
                              "+f"(acc[mi][ni][2]), "+f"(acc[mi][ni][3])
                            : "r"(af[mi][0]), "r"(af[mi][1]),
                              "r"(af[mi][2]), "r"(af[mi][3]),
                              "r"(bf[ni][0]), "r"(bf[ni][1]));
                    }
            }
            __syncthreads();
            st = (st + 1) % 3;
            ahead -= 1;
        }

        // epilogue
        {
            const int m0 = (tile >> 4) * BM;
            const int n0 = (tile & 15) * BN;
#pragma unroll
            for (int mi = 0; mi < 2; ++mi) {
#pragma unroll
                for (int ni = 0; ni < 8; ++ni) {
                    const int r = m0 + wm * 32 + mi * 16 + g;
                    const int c = n0 + wn * 64 + ni * 8 + t4 * 2;
                    float2 v0 = make_float2(acc[mi][ni][0], acc[mi][ni][1]);
                    float2 v1 = make_float2(acc[mi][ni][2], acc[mi][ni][3]);
                    *reinterpret_cast<float2*>(C + (size_t)r * HIDD + c)       = v0;
                    *reinterpret_cast<float2*>(C + (size_t)(r + 8) * HIDD + c) = v1;
                }
            }
        }

        if (next_tile >= NTILES) break;
        tile = next_tile;
    }
}

// ---------------------------------------------------------------------------
extern "C" void kernel_launch(void* const* d_in, const int* in_sizes, int n_in,
                              void* d_out, int out_size) {
    const float* x      = (const float*)d_in[0];
    const float* W      = (const float*)d_in[1];
    const int*   nn_idx = (const int*)  d_in[2];
    const float* sim    = (const float*)d_in[3];
    float*       out    = (float*)d_out;

    int* syncp = nullptr;
    cudaGetSymbolAddress((void**)&syncp, g_sync);

    cudaFuncSetAttribute(fused_kernel,
                         cudaFuncAttributeMaxDynamicSharedMemorySize, GEMM_SMEM);

    cudaMemsetAsync(syncp, 0, sizeof(int) * (2 + 256));
    fused_kernel<<<GRID_CTAS, 256, GEMM_SMEM>>>(x, W, nn_idx, sim, out);
}

// round 14
// speedup vs baseline: 1.0471x; 1.0471x over previous
#include <cuda_runtime.h>
#include <cuda_fp16.h>
#include <cstdint>

// Problem constants
#define CTXD   512
#define HIDD   2048
#define NCELLS 4096      // 64*64
#define NBATCH 8
#define KNN    8
#define MTOT   (NBATCH * NCELLS)   // 32768

// Scratch (allowed: __device__ globals)
__device__ __half g_aggh[(size_t)MTOT * CTXD];  // 32 MB fp16 agg
__device__ __half g_Wh[(size_t)HIDD * CTXD];    // 2 MB  fp16 W^T
__device__ int    g_tile_ctr;

// ---------------------------------------------------------------------------
// Kernel 1: fused prep: agg (4 cells/block) + W transpose->fp16  (R9 proven)
// ---------------------------------------------------------------------------
__global__ __launch_bounds__(128) void prep_kernel(
    const float* __restrict__ x,
    const int*   __restrict__ nn_idx,
    const float* __restrict__ sim,
    const float* __restrict__ W)
{
    const int bid = blockIdx.x;
    const int t   = threadIdx.x;

    if (bid < 8192) {
        const int n0 = (bid & 1023) * 4;
        const int b  = bid >> 10;

        __shared__ int   s_idx[4 * KNN];
        __shared__ float s_sim[4 * KNN];
        if (t < 4 * KNN) {
            s_idx[t] = nn_idx[n0 * KNN + t];
            s_sim[t] = sim[n0 * KNN + t];
        }
        __syncthreads();

        const float4* xb = reinterpret_cast<const float4*>(x) +
                           (size_t)b * NCELLS * (CTXD / 4);
        uint2* dst = reinterpret_cast<uint2*>(g_aggh);

#pragma unroll
        for (int c = 0; c < 4; c++) {
            float4 acc = make_float4(0.f, 0.f, 0.f, 0.f);
#pragma unroll
            for (int k = 0; k < KNN; k++) {
                const float  s = s_sim[c * KNN + k];
                const float4 v = xb[(size_t)s_idx[c * KNN + k] * (CTXD / 4) + t];
                acc.x = fmaf(s, v.x, acc.x);
                acc.y = fmaf(s, v.y, acc.y);
                acc.z = fmaf(s, v.z, acc.z);
                acc.w = fmaf(s, v.w, acc.w);
            }
            __half2 h0 = __float22half2_rn(make_float2(acc.x, acc.y));
            __half2 h1 = __float22half2_rn(make_float2(acc.z, acc.w));
            uint2 p;
            p.x = *reinterpret_cast<uint32_t*>(&h0);
            p.y = *reinterpret_cast<uint32_t*>(&h1);
            dst[((size_t)b * NCELLS + n0 + c) * (CTXD / 4) + t] = p;
        }
    } else {
        const int wb = bid - 8192;
        const int bx = wb & 63;
        const int by = wb >> 6;
        const int tx = t & 31;
        const int ty = t >> 5;

        __shared__ float tile[32][33];
#pragma unroll
        for (int i = 0; i < 8; i++)
            tile[ty + i * 4][tx] =
                W[(size_t)(by * 32 + ty + i * 4) * HIDD + bx * 32 + tx];
        __syncthreads();
#pragma unroll
        for (int i = 0; i < 8; i++)
            g_Wh[(size_t)(bx * 32 + ty + i * 4) * CTXD + by * 32 + tx] =
                __float2half(tile[tx][ty + i * 4]);
    }
}

// ---------------------------------------------------------------------------
// Kernel 2: persistent fp16 mma.sync GEMM, 128x256 CTA tile, 16 warps
// (warp tile 32x64), BK=64, 4-stage cp.async, cross-tile prefetch,
// atomic tile scheduler, fp32 accum, 1 CTA/SM.
// ---------------------------------------------------------------------------
#define BM 128
#define BN 256
#define BK 64
#define NT (CTXD / BK)                        // 8 chunks per tile
#define NTILES ((MTOT / BM) * (HIDD / BN))    // 2048
#define SSTRIDE 72
#define A_TILE_H (BM * SSTRIDE)               // 9216 halves
#define B_TILE_H (BN * SSTRIDE)               // 18432 halves
#define STAGE_H (A_TILE_H + B_TILE_H)         // 27648 halves = 55296 B
#define NSTAGE 4
#define GEMM_SMEM (NSTAGE * STAGE_H * 2)      // 221184 bytes
#define GEMM_CTAS 152

__device__ __forceinline__ void cpasync16(uint32_t saddr, const void* g) {
    asm volatile("cp.async.cg.shared.global [%0], [%1], 16;\n" :: "r"(saddr), "l"(g));
}
__device__ __forceinline__ void ldsm_x4(uint32_t& r0, uint32_t& r1,
                                        uint32_t& r2, uint32_t& r3, uint32_t a) {
    asm volatile("ldmatrix.sync.aligned.m8n8.x4.shared.b16 {%0,%1,%2,%3},[%4];"
                 : "=r"(r0), "=r"(r1), "=r"(r2), "=r"(r3) : "r"(a));
}

__global__ __launch_bounds__(512, 1) void gemm_hmma(
    const __half* __restrict__ A,   // [MTOT][CTXD]
    const __half* __restrict__ B,   // [HIDD][CTXD]  (W^T)
    float*        __restrict__ C)   // [MTOT][HIDD]
{
    extern __shared__ __half sm[];
    __shared__ int sm_next;

    const int tid  = threadIdx.x;
    const int lane = tid & 31;
    const int warp = tid >> 5;      // 0..15
    const int wm   = warp & 3;      // 32-row M quarter
    const int wn   = warp >> 2;     // 64-col N quarter (of 256)
    const int g    = lane >> 2;
    const int t4   = lane & 3;

    // chunk loader: tile + chunk kt -> stage buf
    auto load_chunk = [&](int buf, int tile, int kt) {
        const int m0 = (tile >> 3) * BM;
        const int n0 = (tile & 7) * BN;
        __half* Asb = sm + buf * STAGE_H;
        __half* Bsb = Asb + A_TILE_H;
        const __half* Ag = A + (size_t)m0 * CTXD + kt * BK;
        const __half* Bg = B + (size_t)n0 * CTXD + kt * BK;
#pragma unroll
        for (int i = 0; i < 2; i++) {              // A: 1024 x 16B
            int idx = i * 512 + tid;
            int row = idx >> 3;
            int c8  = (idx & 7) * 8;
            cpasync16((uint32_t)__cvta_generic_to_shared(Asb + row * SSTRIDE + c8),
                      Ag + (size_t)row * CTXD + c8);
        }
#pragma unroll
        for (int i = 0; i < 4; i++) {              // B: 2048 x 16B
            int idx = i * 512 + tid;
            int row = idx >> 3;
            int c8  = (idx & 7) * 8;
            cpasync16((uint32_t)__cvta_generic_to_shared(Bsb + row * SSTRIDE + c8),
                      Bg + (size_t)row * CTXD + c8);
        }
        asm volatile("cp.async.commit_group;\n");
    };

    if (tid == 0) sm_next = atomicAdd(&g_tile_ctr, 1);
    __syncthreads();
    int tile = sm_next;
    if (tile >= NTILES) return;

    // prologue: 3 chunks in flight
    load_chunk(0, tile, 0);
    load_chunk(1, tile, 1);
    load_chunk(2, tile, 2);
    int st = 0;          // buffer of current compute chunk
    int inflight = 3;    // outstanding cp.async groups

    const int a_r  = lane & 15;
    const int a_k  = (lane >> 4) * 8;
    const int b_r  = lane & 7;
    const int b_no = ((lane >> 3) >> 1) * 8;
    const int b_ko = ((lane >> 3) & 1) * 8;

    while (true) {
        float acc[2][8][4];
#pragma unroll
        for (int i = 0; i < 2; i++)
#pragma unroll
            for (int j = 0; j < 8; j++)
#pragma unroll
                for (int r = 0; r < 4; r++) acc[i][j][r] = 0.f;

        int next_tile = NTILES;

        for (int kt = 0; kt < NT; ++kt) {
            // current chunk's group must be complete
            if (inflight >= 3)      asm volatile("cp.async.wait_group 2;\n");
            else if (inflight == 2) asm volatile("cp.async.wait_group 1;\n");
            else                    asm volatile("cp.async.wait_group 0;\n");
            __syncthreads();

            if (kt == 4) {
                if (tid == 0) sm_next = atomicAdd(&g_tile_ctr, 1);
            }
            if (kt == 5) next_tile = sm_next;   // ordered by this iter's sync

            // prefetch chunk 3 ahead (current tile or next tile)
            const int pf = kt + 3;
            const int pbuf = (st + 3) & 3;
            if (pf < NT) {
                load_chunk(pbuf, tile, pf);
            } else if (kt >= 5 && next_tile < NTILES) {
                load_chunk(pbuf, next_tile, pf - NT);
            } else {
                inflight -= 1;
            }

            const __half* Asb = sm + st * STAGE_H;
            const __half* Bsb = Asb + A_TILE_H;

#pragma unroll
            for (int ks = 0; ks < 4; ++ks) {
                const int k0 = ks * 16;

                uint32_t af[2][4];
#pragma unroll
                for (int mi = 0; mi < 2; ++mi) {
                    uint32_t a = (uint32_t)__cvta_generic_to_shared(
                        Asb + (wm * 32 + mi * 16 + a_r) * SSTRIDE + k0 + a_k);
                    ldsm_x4(af[mi][0], af[mi][1], af[mi][2], af[mi][3], a);
                }
                uint32_t bf[8][2];
#pragma unroll
                for (int nj = 0; nj < 4; ++nj) {
                    uint32_t a = (uint32_t)__cvta_generic_to_shared(
                        Bsb + (wn * 64 + nj * 16 + b_no + b_r) * SSTRIDE + k0 + b_ko);
                    ldsm_x4(bf[2 * nj][0], bf[2 * nj][1],
                            bf[2 * nj + 1][0], bf[2 * nj + 1][1], a);
                }
#pragma unroll
                for (int mi = 0; mi < 2; ++mi)
#pragma unroll
                    for (int ni = 0; ni < 8; ++ni) {
                        asm volatile(
                            "mma.sync.aligned.m16n8k16.row.col.f32.f16.f16.f32 "
                            "{%0,%1,%2,%3},{%4,%5,%6,%7},{%8,%9},{%0,%1,%2,%3};\n"
                            : "+f"(acc[mi][ni][0]), "+f"(acc[mi][ni][1]),
                              "+f"(acc[mi][ni][2]), "+f"(acc[mi][ni][3])
                            : "r"(af[mi][0]), "r"(af[mi][1]),
                              "r"(af[mi][2]), "r"(af[mi][3]),
                              "r"(bf[ni][0]), "r"(bf[ni][1]));
                    }
            }
            __syncthreads();
            st = (st + 1) & 3;
        }

        // epilogue
        {
            const int m0 = (tile >> 3) * BM;
            const int n0 = (tile & 7) * BN;
#pragma unroll
            for (int mi = 0; mi < 2; ++mi) {
#pragma unroll
                for (int ni = 0; ni < 8; ++ni) {
                    const int r = m0 + wm * 32 + mi * 16 + g;
                    const int c = n0 + wn * 64 + ni * 8 + t4 * 2;
                    float2 v0 = make_float2(acc[mi][ni][0], acc[mi][ni][1]);
                    float2 v1 = make_float2(acc[mi][ni][2], acc[mi][ni][3]);
                    *reinterpret_cast<float2*>(C + (size_t)r * HIDD + c)       = v0;
                    *reinterpret_cast<float2*>(C + (size_t)(r + 8) * HIDD + c) = v1;
                }
            }
        }

        if (next_tile >= NTILES) break;
        tile = next_tile;
    }
}

// ---------------------------------------------------------------------------
extern "C" void kernel_launch(void* const* d_in, const int* in_sizes, int n_in,
                              void* d_out, int out_size) {
    const float* x      = (const float*)d_in[0];
    const float* W      = (const float*)d_in[1];
    const int*   nn_idx = (const int*)  d_in[2];
    const float* sim    = (const float*)d_in[3];
    float*       out    = (float*)d_out;

    __half* aggh = nullptr;
    __half* wh   = nullptr;
    int*    ctr  = nullptr;
    cudaGetSymbolAddress((void**)&aggh, g_aggh);
    cudaGetSymbolAddress((void**)&wh,   g_Wh);
    cudaGetSymbolAddress((void**)&ctr,  g_tile_ctr);

    cudaFuncSetAttribute(gemm_hmma,
                         cudaFuncAttributeMaxDynamicSharedMemorySize, GEMM_SMEM);

    cudaMemsetAsync(ctr, 0, sizeof(int));
    prep_kernel<<<8192 + 1024, 128>>>(x, nn_idx, sim, W);
    gemm_hmma<<<GEMM_CTAS, 512, GEMM_SMEM>>>(aggh, wh, out);
}